// round 12
// baseline (speedup 1.0000x reference)
#include <cuda_runtime.h>
#include <cuda_bf16.h>
#include <cuda_fp16.h>
#include <cstddef>

#define NMAX   100000
#define EMAX   3200000
#define DOUT   64
#define FIN    256
#define NBMAX  128

// Scratch (__device__ globals: zero-initialized at load).
// Invariants restored every call: g_ecnt=0, g_flag=0 (by aggregate),
// g_scan_pack zeroed by prep before scan uses it.
__device__ float  g_xw [NMAX * DOUT];
__device__ __half g_xwh[NMAX * DOUT];
__device__ float  g_out[NMAX * DOUT];
__device__ float  g_dinv[NMAX];
__device__ int    g_ecnt[NMAX];
__device__ int    g_off [NMAX];
__device__ int    g_cur [NMAX];
__device__ int    g_flag[NMAX];
__device__ int    g_csr [EMAX];
__device__ unsigned long long g_scan_pack[NBMAX];  // status(hi32) | value(lo32)
__device__ __nv_bfloat16 g_wth[DOUT * FIN];
__device__ __nv_bfloat16 g_wtl[DOUT * FIN];

// ---------------------------------------------------------------------------
__device__ __forceinline__ unsigned pack_bf2(float x, float y) {
    __nv_bfloat162 t = __floats2bfloat162_rn(x, y);
    return *reinterpret_cast<unsigned*>(&t);
}

__device__ __forceinline__ void ldsm4(unsigned* r, unsigned addr) {
    asm volatile("ldmatrix.sync.aligned.m8n8.x4.shared.b16 {%0,%1,%2,%3}, [%4];\n"
                 : "=r"(r[0]), "=r"(r[1]), "=r"(r[2]), "=r"(r[3]) : "r"(addr));
}

__device__ __forceinline__ void mma_bf16(float* c, const unsigned* a,
                                         unsigned b0, unsigned b1) {
    asm volatile("mma.sync.aligned.m16n8k16.row.col.f32.bf16.bf16.f32 "
                 "{%0,%1,%2,%3}, {%4,%5,%6,%7}, {%8,%9}, {%0,%1,%2,%3};\n"
                 : "+f"(c[0]), "+f"(c[1]), "+f"(c[2]), "+f"(c[3])
                 : "r"(a[0]), "r"(a[1]), "r"(a[2]), "r"(a[3]), "r"(b0), "r"(b1));
}

// ---------------------------------------------------------------------------
// 1) prep: degree (role 0) + wsplit (role 1) + flag-mark (role 2) + pack-zero
// ---------------------------------------------------------------------------
__global__ void prep_kernel(const int* __restrict__ dst, int e,
                            const float* __restrict__ W,
                            const int* __restrict__ x, int nx,
                            int nDeg, int nFlag) {
    int bx = blockIdx.x;
    int tid = threadIdx.x;

    if (bx < nDeg) {
        // ---- degree ----
        int i4 = (bx * 256 + tid) * 4;
        if (i4 + 3 < e) {
            int4 d = *reinterpret_cast<const int4*>(dst + i4);
            atomicAdd(&g_ecnt[d.x], 1);
            atomicAdd(&g_ecnt[d.y], 1);
            atomicAdd(&g_ecnt[d.z], 1);
            atomicAdd(&g_ecnt[d.w], 1);
        } else if (i4 < e) {
            for (int j = i4; j < e; j++) atomicAdd(&g_ecnt[dst[j]], 1);
        }
    } else if (bx < nDeg + 64) {
        // ---- wsplit: W^T hi/lo bf16 ----
        int idx = (bx - nDeg) * 256 + tid;   // 0..16383
        int k = idx >> 6, n = idx & 63;
        float a = W[idx];
        __nv_bfloat16 h = __float2bfloat16(a);
        float r = a - __bfloat162float(h);
        g_wth[n * FIN + k] = h;
        g_wtl[n * FIN + k] = __float2bfloat16(r);
    } else if (bx < nDeg + 64 + nFlag) {
        // ---- flag-mark nodes referenced by x ----
        int i4 = ((bx - nDeg - 64) * 256 + tid) * 4;
        if (i4 + 3 < nx) {
            int4 v = *reinterpret_cast<const int4*>(x + i4);
            g_flag[v.x] = 1;
            g_flag[v.y] = 1;
            g_flag[v.z] = 1;
            g_flag[v.w] = 1;
        } else if (i4 < nx) {
            for (int j = i4; j < nx; j++) g_flag[x[j]] = 1;
        }
    } else {
        // ---- zero scan packs ----
        if (tid < NBMAX) g_scan_pack[tid] = 0ull;
    }
}

// ---------------------------------------------------------------------------
// 2) single-pass scan (decoupled lookback, PACKED status|value) + dinv.
//    1024 elems/block.  status: 0=invalid 1=aggregate 2=inclusive-prefix.
// ---------------------------------------------------------------------------
__global__ void __launch_bounds__(256) scan_kernel(int n) {
    __shared__ int warp_sums[8];
    __shared__ int s_prefix;
    int blk = blockIdx.x, tid = threadIdx.x;
    int base = blk * 1024 + tid * 4;
    int v[4];
#pragma unroll
    for (int j = 0; j < 4; j++) v[j] = (base + j < n) ? g_ecnt[base + j] : 0;
#pragma unroll
    for (int j = 0; j < 4; j++)
        if (base + j < n) g_dinv[base + j] = rsqrtf((float)(v[j] + 1));
    int tsum = v[0] + v[1] + v[2] + v[3];
    int lane = tid & 31, wid = tid >> 5;
    int x = tsum;
#pragma unroll
    for (int o = 1; o < 32; o <<= 1) {
        int y = __shfl_up_sync(~0u, x, o);
        if (lane >= o) x += y;
    }
    if (lane == 31) warp_sums[wid] = x;
    __syncthreads();
    if (wid == 0) {
        int w = (lane < 8) ? warp_sums[lane] : 0;
#pragma unroll
        for (int o = 1; o < 8; o <<= 1) {
            int y = __shfl_up_sync(~0u, w, o);
            if (lane >= o) w += y;
        }
        if (lane < 8) warp_sums[lane] = w;
    }
    __syncthreads();
    int excl = x - tsum + (wid > 0 ? warp_sums[wid - 1] : 0);

    // decoupled lookback (tid 0) — status+value in ONE 64-bit word
    if (tid == 0) {
        int total = warp_sums[7];
        if (blk == 0) {
            atomicExch(&g_scan_pack[0], (2ull << 32) | (unsigned)total);
            s_prefix = 0;
        } else {
            atomicExch(&g_scan_pack[blk], (1ull << 32) | (unsigned)total);
            int run = 0, p = blk - 1;
            while (true) {
                unsigned long long w;
                do { w = atomicAdd(&g_scan_pack[p], 0ull); } while ((w >> 32) == 0);
                run += (int)(unsigned)w;
                if ((w >> 32) == 2ull) break;
                p--;
            }
            atomicExch(&g_scan_pack[blk], (2ull << 32) | (unsigned)(total + run));
            s_prefix = run;
        }
    }
    __syncthreads();
    int pre = s_prefix;

    int run = pre + excl;
#pragma unroll
    for (int j = 0; j < 4; j++) {
        if (base + j < n) {
            g_off[base + j] = run;
            g_cur[base + j] = run;
        }
        run += v[j];
    }
}

// ---------------------------------------------------------------------------
// 3) fused GEMM + CSR-fill.  bx%5==0 -> GEMM; else fill.
//    Epilogue writes fp32 xw and fp16 xwh = half(xw*dinv[row]).
// ---------------------------------------------------------------------------
__global__ void __launch_bounds__(256, 2) gemm_fill_kernel(
        const float* __restrict__ A, int M,
        const int* __restrict__ src, const int* __restrict__ dst, int e) {
    __shared__ __align__(16) __nv_bfloat16 Wh[64 * 136];
    __shared__ __align__(16) __nv_bfloat16 Wl[64 * 136];

    const int bx = blockIdx.x;

    if ((bx % 5) != 0) {
        // ---- fill role ----
        int fb = (bx / 5) * 4 + (bx % 5) - 1;
        int i4 = (fb * 256 + threadIdx.x) * 4;
        if (i4 + 3 < e) {
            int4 d = *reinterpret_cast<const int4*>(dst + i4);
            int4 s = *reinterpret_cast<const int4*>(src + i4);
            int p0 = atomicAdd(&g_cur[d.x], 1);
            int p1 = atomicAdd(&g_cur[d.y], 1);
            int p2 = atomicAdd(&g_cur[d.z], 1);
            int p3 = atomicAdd(&g_cur[d.w], 1);
            g_csr[p0] = s.x;
            g_csr[p1] = s.y;
            g_csr[p2] = s.z;
            g_csr[p3] = s.w;
        } else if (i4 < e) {
            for (int j = i4; j < e; j++) {
                int d = dst[j];
                int pos = atomicAdd(&g_cur[d], 1);
                g_csr[pos] = src[j];
            }
        }
        return;
    }

    // ---- GEMM role ----
    const int tid  = threadIdx.x;
    const int lane = tid & 31;
    const int wid  = tid >> 5;
    const int bm   = (bx / 5) * 128;

    const int  r0 = bm + wid * 16 + (lane >> 2);
    const int  r1 = r0 + 8;
    const bool v0 = r0 < M;
    const bool v1 = r1 < M;
    const int  c0 = (lane & 3) * 2;

    const float* pA0 = A + (size_t)r0 * FIN + c0;
    const float* pA1 = A + (size_t)r1 * FIN + c0;

    const unsigned wh_base = (unsigned)__cvta_generic_to_shared(Wh);
    const unsigned wl_base = (unsigned)__cvta_generic_to_shared(Wl);
    const int n_off = (lane & 7) + ((lane >> 4) & 1) * 8;
    const int k_off = ((lane >> 3) & 1) * 8;

    float acc[8][4];
#pragma unroll
    for (int t = 0; t < 8; t++)
#pragma unroll
        for (int j = 0; j < 4; j++) acc[t][j] = 0.f;

    const float2 Z = make_float2(0.f, 0.f);
    float2 cur[4], nxt[4];
    cur[0] = v0 ? *reinterpret_cast<const float2*>(pA0)     : Z;
    cur[1] = v1 ? *reinterpret_cast<const float2*>(pA1)     : Z;
    cur[2] = v0 ? *reinterpret_cast<const float2*>(pA0 + 8) : Z;
    cur[3] = v1 ? *reinterpret_cast<const float2*>(pA1 + 8) : Z;

    for (int kc = 0; kc < 2; kc++) {
        __syncthreads();
        for (int i = tid; i < 1024; i += 256) {
            int row = i >> 4, seg = i & 15;
            *reinterpret_cast<uint4*>(Wh + row * 136 + seg * 8) =
                *reinterpret_cast<const uint4*>(g_wth + row * 256 + kc * 128 + seg * 8);
            *reinterpret_cast<uint4*>(Wl + row * 136 + seg * 8) =
                *reinterpret_cast<const uint4*>(g_wtl + row * 256 + kc * 128 + seg * 8);
        }
        __syncthreads();

#pragma unroll
        for (int k16 = 0; k16 < 8; k16++) {
            int kn = kc * 128 + k16 * 16 + 16;
            if (kn < FIN) {
                nxt[0] = v0 ? *reinterpret_cast<const float2*>(pA0 + kn)     : Z;
                nxt[1] = v1 ? *reinterpret_cast<const float2*>(pA1 + kn)     : Z;
                nxt[2] = v0 ? *reinterpret_cast<const float2*>(pA0 + kn + 8) : Z;
                nxt[3] = v1 ? *reinterpret_cast<const float2*>(pA1 + kn + 8) : Z;
            }

            unsigned ah[4], al[4];
#pragma unroll
            for (int j = 0; j < 4; j++) {
                float x = cur[j].x, y = cur[j].y;
                __nv_bfloat16 hx = __float2bfloat16(x);
                __nv_bfloat16 hy = __float2bfloat16(y);
                __nv_bfloat162 hp; hp.x = hx; hp.y = hy;
                ah[j] = *reinterpret_cast<unsigned*>(&hp);
                al[j] = pack_bf2(x - __bfloat162float(hx), y - __bfloat162float(hy));
            }

#pragma unroll
            for (int p = 0; p < 4; p++) {
                unsigned boff = (unsigned)(((p * 16 + n_off) * 136 + k16 * 16 + k_off) * 2);
                unsigned bh[4], bl[4];
                ldsm4(bh, wh_base + boff);
                ldsm4(bl, wl_base + boff);
                mma_bf16(acc[2 * p],     ah, bh[0], bh[1]);
                mma_bf16(acc[2 * p],     al, bh[0], bh[1]);
                mma_bf16(acc[2 * p],     ah, bl[0], bl[1]);
                mma_bf16(acc[2 * p + 1], ah, bh[2], bh[3]);
                mma_bf16(acc[2 * p + 1], al, bh[2], bh[3]);
                mma_bf16(acc[2 * p + 1], ah, bl[2], bl[3]);
            }
#pragma unroll
            for (int j = 0; j < 4; j++) cur[j] = nxt[j];
        }
    }

    float dv0 = v0 ? g_dinv[r0] : 0.f;
    float dv1 = v1 ? g_dinv[r1] : 0.f;
#pragma unroll
    for (int nt = 0; nt < 8; nt++) {
        int col = nt * 8 + c0;
        if (v0) {
            float2 w = make_float2(acc[nt][0], acc[nt][1]);
            *reinterpret_cast<float2*>(g_xw + (size_t)r0 * DOUT + col) = w;
            __half2 h = __float22half2_rn(make_float2(w.x * dv0, w.y * dv0));
            *reinterpret_cast<__half2*>(g_xwh + (size_t)r0 * DOUT + col) = h;
        }
        if (v1) {
            float2 w = make_float2(acc[nt][2], acc[nt][3]);
            *reinterpret_cast<float2*>(g_xw + (size_t)r1 * DOUT + col) = w;
            __half2 h = __float22half2_rn(make_float2(w.x * dv1, w.y * dv1));
            *reinterpret_cast<__half2*>(g_xwh + (size_t)r1 * DOUT + col) = h;
        }
    }
}

// ---------------------------------------------------------------------------
// 4) aggregate: one warp per node; only flagged nodes do work.
//    Resets g_ecnt and g_flag (invariants for next call).
// ---------------------------------------------------------------------------
__global__ void __launch_bounds__(256) aggregate_kernel(const float* __restrict__ b,
                                                        int n) {
    int node = (blockIdx.x * blockDim.x + threadIdx.x) >> 5;
    int lane = threadIdx.x & 31;
    if (node >= n) return;

    int flg = g_flag[node];
    float dn    = g_dinv[node];
    int   start = g_off[node];
    int   end   = start + g_ecnt[node];
    if (lane == 0) {
        g_ecnt[node] = 0;
        g_flag[node] = 0;
    }
    if (!flg) return;

    float2 w = *reinterpret_cast<const float2*>(g_xw + ((size_t)node << 6) + (lane << 1));
    float2 sum = make_float2(0.f, 0.f);

    int j = start;
    for (; j + 3 < end; j += 4) {
        int s0 = g_csr[j], s1 = g_csr[j + 1], s2 = g_csr[j + 2], s3 = g_csr[j + 3];
        __half2 h0 = *reinterpret_cast<const __half2*>(g_xwh + ((size_t)s0 << 6) + (lane << 1));
        __half2 h1 = *reinterpret_cast<const __half2*>(g_xwh + ((size_t)s1 << 6) + (lane << 1));
        __half2 h2 = *reinterpret_cast<const __half2*>(g_xwh + ((size_t)s2 << 6) + (lane << 1));
        __half2 h3 = *reinterpret_cast<const __half2*>(g_xwh + ((size_t)s3 << 6) + (lane << 1));
        float2 f0 = __half22float2(h0), f1 = __half22float2(h1);
        float2 f2 = __half22float2(h2), f3 = __half22float2(h3);
        sum.x += f0.x + f1.x + f2.x + f3.x;
        sum.y += f0.y + f1.y + f2.y + f3.y;
    }
    for (; j < end; j++) {
        int s = g_csr[j];
        __half2 h = *reinterpret_cast<const __half2*>(g_xwh + ((size_t)s << 6) + (lane << 1));
        float2 f = __half22float2(h);
        sum.x += f.x; sum.y += f.y;
    }

    float  sl = dn * dn;
    float2 bb = *reinterpret_cast<const float2*>(b + (lane << 1));
    float2 r  = make_float2(w.x * sl + dn * sum.x + bb.x,
                            w.y * sl + dn * sum.y + bb.y);
    *reinterpret_cast<float2*>(g_out + ((size_t)node << 6) + (lane << 1)) = r;
}

// ---------------------------------------------------------------------------
// 5) final gather
// ---------------------------------------------------------------------------
__global__ void gather_kernel(const int* __restrict__ x,
                              float* __restrict__ out, int nidx) {
    int idx = blockIdx.x * blockDim.x + threadIdx.x;
    int i = idx >> 4;
    int q = idx & 15;
    if (i >= nidx) return;
    int nd = x[i];
    float4 v = *reinterpret_cast<const float4*>(g_out + ((size_t)nd << 6) + (q << 2));
    *reinterpret_cast<float4*>(out + ((size_t)i << 6) + (q << 2)) = v;
}

// ---------------------------------------------------------------------------
extern "C" void kernel_launch(void* const* d_in, const int* in_sizes, int n_in,
                              void* d_out, int out_size) {
    const float* features   = (const float*)d_in[0];
    const int*   edge_index = (const int*)  d_in[1];
    const float* W          = (const float*)d_in[2];
    const float* b          = (const float*)d_in[3];
    const int*   x          = (const int*)  d_in[4];
    float*       out        = (float*)d_out;

    const int N  = in_sizes[0] / FIN;
    const int E  = in_sizes[1] / 2;
    const int NX = in_sizes[4];

    const int* src = edge_index;
    const int* dst = edge_index + E;
    const int NB = (N + 1023) / 1024;

    int nDeg  = (E + 1023) / 1024;
    int nFlag = (NX + 1023) / 1024;
    prep_kernel<<<nDeg + 64 + nFlag + 1, 256>>>(dst, E, W, x, NX, nDeg, nFlag);

    scan_kernel<<<NB, 256>>>(N);

    int nGemm = (N + 127) / 128;
    int nFillNeeded = (E + 1023) / 1024;
    if (nGemm * 4 < nFillNeeded) nGemm = (nFillNeeded + 3) / 4;
    gemm_fill_kernel<<<nGemm * 5, 256>>>(features, N, src, dst, E);

    long long agg_threads = (long long)N * 32;
    aggregate_kernel<<<(int)((agg_threads + 255) / 256), 256>>>(b, N);

    gather_kernel<<<(NX * 16 + 255) / 256, 256>>>(x, out, NX);
}

// round 13
// speedup vs baseline: 2.4851x; 2.4851x over previous
#include <cuda_runtime.h>
#include <cuda_bf16.h>
#include <cuda_fp16.h>
#include <cstddef>

#define NMAX   100000
#define EMAX   3200000
#define DOUT   64
#define FIN    256
#define NBMAX  128

// Scratch (__device__ globals: zero-initialized at load).
// Invariant restored every call: g_ecnt == 0 (reset by aggregate_kernel).
__device__ float  g_xw [NMAX * DOUT];
__device__ __half g_xwh[NMAX * DOUT];
__device__ float  g_out[NMAX * DOUT];
__device__ float  g_dinv[NMAX];
__device__ int    g_ecnt[NMAX];
__device__ int    g_off [NMAX];
__device__ int    g_cur [NMAX];
__device__ int    g_csr [EMAX];
__device__ int    g_bsum[NBMAX];
__device__ int    g_bscan[NBMAX];
__device__ __nv_bfloat16 g_wth[DOUT * FIN];
__device__ __nv_bfloat16 g_wtl[DOUT * FIN];

// ---------------------------------------------------------------------------
__device__ __forceinline__ unsigned pack_bf2(float x, float y) {
    __nv_bfloat162 t = __floats2bfloat162_rn(x, y);
    return *reinterpret_cast<unsigned*>(&t);
}

__device__ __forceinline__ void ldsm4(unsigned* r, unsigned addr) {
    asm volatile("ldmatrix.sync.aligned.m8n8.x4.shared.b16 {%0,%1,%2,%3}, [%4];\n"
                 : "=r"(r[0]), "=r"(r[1]), "=r"(r[2]), "=r"(r[3]) : "r"(addr));
}

__device__ __forceinline__ void mma_bf16(float* c, const unsigned* a,
                                         unsigned b0, unsigned b1) {
    asm volatile("mma.sync.aligned.m16n8k16.row.col.f32.bf16.bf16.f32 "
                 "{%0,%1,%2,%3}, {%4,%5,%6,%7}, {%8,%9}, {%0,%1,%2,%3};\n"
                 : "+f"(c[0]), "+f"(c[1]), "+f"(c[2]), "+f"(c[3])
                 : "r"(a[0]), "r"(a[1]), "r"(a[2]), "r"(a[3]), "r"(b0), "r"(b1));
}

// ---------------------------------------------------------------------------
// 1) fused degree + wsplit.  bx < nDeg -> degree (4 edges/thread);
//    else wsplit (W^T hi/lo bf16).  g_ecnt arrives zeroed (invariant).
// ---------------------------------------------------------------------------
__global__ void degwsplit_kernel(const int* __restrict__ dst, int e,
                                 const float* __restrict__ W, int nDeg) {
    int bx = blockIdx.x;
    int tid = threadIdx.x;

    if (bx < nDeg) {
        int i4 = (bx * 256 + tid) * 4;
        if (i4 + 3 < e) {
            int4 d = *reinterpret_cast<const int4*>(dst + i4);
            atomicAdd(&g_ecnt[d.x], 1);
            atomicAdd(&g_ecnt[d.y], 1);
            atomicAdd(&g_ecnt[d.z], 1);
            atomicAdd(&g_ecnt[d.w], 1);
        } else if (i4 < e) {
            for (int j = i4; j < e; j++) atomicAdd(&g_ecnt[dst[j]], 1);
        }
    } else {
        int idx = (bx - nDeg) * 256 + tid;   // 0..16383
        int k = idx >> 6, n = idx & 63;
        float a = W[idx];
        __nv_bfloat16 h = __float2bfloat16(a);
        float r = a - __bfloat162float(h);
        g_wth[n * FIN + k] = h;
        g_wtl[n * FIN + k] = __float2bfloat16(r);
    }
}

// ---------------------------------------------------------------------------
// 2) scan pass 1 (+ dinv fused)
// ---------------------------------------------------------------------------
__global__ void scan1_kernel(int n) {
    __shared__ int warp_sums[8];
    int blk = blockIdx.x, tid = threadIdx.x;
    int base = blk * 1024 + tid * 4;
    int v[4];
#pragma unroll
    for (int j = 0; j < 4; j++) v[j] = (base + j < n) ? g_ecnt[base + j] : 0;
#pragma unroll
    for (int j = 0; j < 4; j++)
        if (base + j < n) g_dinv[base + j] = rsqrtf((float)(v[j] + 1));
    int tsum = v[0] + v[1] + v[2] + v[3];
    int lane = tid & 31, wid = tid >> 5;
    int x = tsum;
#pragma unroll
    for (int o = 1; o < 32; o <<= 1) {
        int y = __shfl_up_sync(~0u, x, o);
        if (lane >= o) x += y;
    }
    if (lane == 31) warp_sums[wid] = x;
    __syncthreads();
    if (wid == 0) {
        int w = (lane < 8) ? warp_sums[lane] : 0;
#pragma unroll
        for (int o = 1; o < 8; o <<= 1) {
            int y = __shfl_up_sync(~0u, w, o);
            if (lane >= o) w += y;
        }
        if (lane < 8) warp_sums[lane] = w;
    }
    __syncthreads();
    int excl = x - tsum + (wid > 0 ? warp_sums[wid - 1] : 0);
    int run = excl;
#pragma unroll
    for (int j = 0; j < 4; j++) {
        if (base + j < n) g_off[base + j] = run;
        run += v[j];
    }
    if (tid == 0) g_bsum[blk] = warp_sums[7];
}

__global__ void scan2_kernel(int nb) {
    __shared__ int ws[4];
    int tid = threadIdx.x, lane = tid & 31, wid = tid >> 5;
    int v = (tid < nb) ? g_bsum[tid] : 0;
    int x = v;
#pragma unroll
    for (int o = 1; o < 32; o <<= 1) {
        int y = __shfl_up_sync(~0u, x, o);
        if (lane >= o) x += y;
    }
    if (lane == 31) ws[wid] = x;
    __syncthreads();
    if (tid == 0) {
        int s = 0;
        for (int i = 0; i < 4; i++) { int t = ws[i]; ws[i] = s; s += t; }
    }
    __syncthreads();
    if (tid < NBMAX) g_bscan[tid] = x - v + ws[wid];
}

__global__ void scan3_kernel(int n) {
    int i = blockIdx.x * blockDim.x + threadIdx.x;
    if (i < n) {
        int o = g_off[i] + g_bscan[i >> 10];
        g_off[i] = o;
        g_cur[i] = o;
    }
}

// ---------------------------------------------------------------------------
// 3) fused GEMM + CSR-fill (R7 proven).  bx%5==0 -> GEMM; else fill.
//    Epilogue writes fp32 xw and fp16 xwh = half(xw*dinv[row]).
// ---------------------------------------------------------------------------
__global__ void __launch_bounds__(256, 2) gemm_fill_kernel(
        const float* __restrict__ A, int M,
        const int* __restrict__ src, const int* __restrict__ dst, int e) {
    __shared__ __align__(16) __nv_bfloat16 Wh[64 * 136];
    __shared__ __align__(16) __nv_bfloat16 Wl[64 * 136];

    const int bx = blockIdx.x;

    if ((bx % 5) != 0) {
        // ---- fill role ----
        int fb = (bx / 5) * 4 + (bx % 5) - 1;
        int i4 = (fb * 256 + threadIdx.x) * 4;
        if (i4 + 3 < e) {
            int4 d = *reinterpret_cast<const int4*>(dst + i4);
            int4 s = *reinterpret_cast<const int4*>(src + i4);
            int p0 = atomicAdd(&g_cur[d.x], 1);
            int p1 = atomicAdd(&g_cur[d.y], 1);
            int p2 = atomicAdd(&g_cur[d.z], 1);
            int p3 = atomicAdd(&g_cur[d.w], 1);
            g_csr[p0] = s.x;
            g_csr[p1] = s.y;
            g_csr[p2] = s.z;
            g_csr[p3] = s.w;
        } else if (i4 < e) {
            for (int j = i4; j < e; j++) {
                int d = dst[j];
                int pos = atomicAdd(&g_cur[d], 1);
                g_csr[pos] = src[j];
            }
        }
        return;
    }

    // ---- GEMM role ----
    const int tid  = threadIdx.x;
    const int lane = tid & 31;
    const int wid  = tid >> 5;
    const int bm   = (bx / 5) * 128;

    const int  r0 = bm + wid * 16 + (lane >> 2);
    const int  r1 = r0 + 8;
    const bool v0 = r0 < M;
    const bool v1 = r1 < M;
    const int  c0 = (lane & 3) * 2;

    const float* pA0 = A + (size_t)r0 * FIN + c0;
    const float* pA1 = A + (size_t)r1 * FIN + c0;

    const unsigned wh_base = (unsigned)__cvta_generic_to_shared(Wh);
    const unsigned wl_base = (unsigned)__cvta_generic_to_shared(Wl);
    const int n_off = (lane & 7) + ((lane >> 4) & 1) * 8;
    const int k_off = ((lane >> 3) & 1) * 8;

    float acc[8][4];
#pragma unroll
    for (int t = 0; t < 8; t++)
#pragma unroll
        for (int j = 0; j < 4; j++) acc[t][j] = 0.f;

    const float2 Z = make_float2(0.f, 0.f);
    float2 cur[4], nxt[4];
    cur[0] = v0 ? *reinterpret_cast<const float2*>(pA0)     : Z;
    cur[1] = v1 ? *reinterpret_cast<const float2*>(pA1)     : Z;
    cur[2] = v0 ? *reinterpret_cast<const float2*>(pA0 + 8) : Z;
    cur[3] = v1 ? *reinterpret_cast<const float2*>(pA1 + 8) : Z;

    for (int kc = 0; kc < 2; kc++) {
        __syncthreads();
        for (int i = tid; i < 1024; i += 256) {
            int row = i >> 4, seg = i & 15;
            *reinterpret_cast<uint4*>(Wh + row * 136 + seg * 8) =
                *reinterpret_cast<const uint4*>(g_wth + row * 256 + kc * 128 + seg * 8);
            *reinterpret_cast<uint4*>(Wl + row * 136 + seg * 8) =
                *reinterpret_cast<const uint4*>(g_wtl + row * 256 + kc * 128 + seg * 8);
        }
        __syncthreads();

#pragma unroll
        for (int k16 = 0; k16 < 8; k16++) {
            int kn = kc * 128 + k16 * 16 + 16;
            if (kn < FIN) {
                nxt[0] = v0 ? *reinterpret_cast<const float2*>(pA0 + kn)     : Z;
                nxt[1] = v1 ? *reinterpret_cast<const float2*>(pA1 + kn)     : Z;
                nxt[2] = v0 ? *reinterpret_cast<const float2*>(pA0 + kn + 8) : Z;
                nxt[3] = v1 ? *reinterpret_cast<const float2*>(pA1 + kn + 8) : Z;
            }

            unsigned ah[4], al[4];
#pragma unroll
            for (int j = 0; j < 4; j++) {
                float x = cur[j].x, y = cur[j].y;
                __nv_bfloat16 hx = __float2bfloat16(x);
                __nv_bfloat16 hy = __float2bfloat16(y);
                __nv_bfloat162 hp; hp.x = hx; hp.y = hy;
                ah[j] = *reinterpret_cast<unsigned*>(&hp);
                al[j] = pack_bf2(x - __bfloat162float(hx), y - __bfloat162float(hy));
            }

#pragma unroll
            for (int p = 0; p < 4; p++) {
                unsigned boff = (unsigned)(((p * 16 + n_off) * 136 + k16 * 16 + k_off) * 2);
                unsigned bh[4], bl[4];
                ldsm4(bh, wh_base + boff);
                ldsm4(bl, wl_base + boff);
                mma_bf16(acc[2 * p],     ah, bh[0], bh[1]);
                mma_bf16(acc[2 * p],     al, bh[0], bh[1]);
                mma_bf16(acc[2 * p],     ah, bl[0], bl[1]);
                mma_bf16(acc[2 * p + 1], ah, bh[2], bh[3]);
                mma_bf16(acc[2 * p + 1], al, bh[2], bh[3]);
                mma_bf16(acc[2 * p + 1], ah, bl[2], bl[3]);
            }
#pragma unroll
            for (int j = 0; j < 4; j++) cur[j] = nxt[j];
        }
    }

    float dv0 = v0 ? g_dinv[r0] : 0.f;
    float dv1 = v1 ? g_dinv[r1] : 0.f;
#pragma unroll
    for (int nt = 0; nt < 8; nt++) {
        int col = nt * 8 + c0;
        if (v0) {
            float2 w = make_float2(acc[nt][0], acc[nt][1]);
            *reinterpret_cast<float2*>(g_xw + (size_t)r0 * DOUT + col) = w;
            __half2 h = __float22half2_rn(make_float2(w.x * dv0, w.y * dv0));
            *reinterpret_cast<__half2*>(g_xwh + (size_t)r0 * DOUT + col) = h;
        }
        if (v1) {
            float2 w = make_float2(acc[nt][2], acc[nt][3]);
            *reinterpret_cast<float2*>(g_xw + (size_t)r1 * DOUT + col) = w;
            __half2 h = __float22half2_rn(make_float2(w.x * dv1, w.y * dv1));
            *reinterpret_cast<__half2*>(g_xwh + (size_t)r1 * DOUT + col) = h;
        }
    }
}

// ---------------------------------------------------------------------------
// 4) aggregate: one warp per node (NO gating), fp16 messages, fp32 accum.
//    Resets g_ecnt[node]=0 (invariant for next call).
// ---------------------------------------------------------------------------
__global__ void __launch_bounds__(256) aggregate_kernel(const float* __restrict__ b,
                                                        int n) {
    int node = (blockIdx.x * blockDim.x + threadIdx.x) >> 5;
    int lane = threadIdx.x & 31;
    if (node >= n) return;

    float dn    = g_dinv[node];
    int   start = g_off[node];
    int   end   = start + g_ecnt[node];
    if (lane == 0) g_ecnt[node] = 0;   // restore zero-invariant

    float2 w = *reinterpret_cast<const float2*>(g_xw + ((size_t)node << 6) + (lane << 1));
    float2 sum = make_float2(0.f, 0.f);

    int j = start;
    for (; j + 3 < end; j += 4) {
        int s0 = g_csr[j], s1 = g_csr[j + 1], s2 = g_csr[j + 2], s3 = g_csr[j + 3];
        __half2 h0 = *reinterpret_cast<const __half2*>(g_xwh + ((size_t)s0 << 6) + (lane << 1));
        __half2 h1 = *reinterpret_cast<const __half2*>(g_xwh + ((size_t)s1 << 6) + (lane << 1));
        __half2 h2 = *reinterpret_cast<const __half2*>(g_xwh + ((size_t)s2 << 6) + (lane << 1));
        __half2 h3 = *reinterpret_cast<const __half2*>(g_xwh + ((size_t)s3 << 6) + (lane << 1));
        float2 f0 = __half22float2(h0), f1 = __half22float2(h1);
        float2 f2 = __half22float2(h2), f3 = __half22float2(h3);
        sum.x += f0.x + f1.x + f2.x + f3.x;
        sum.y += f0.y + f1.y + f2.y + f3.y;
    }
    for (; j < end; j++) {
        int s = g_csr[j];
        __half2 h = *reinterpret_cast<const __half2*>(g_xwh + ((size_t)s << 6) + (lane << 1));
        float2 f = __half22float2(h);
        sum.x += f.x; sum.y += f.y;
    }

    float  sl = dn * dn;
    float2 bb = *reinterpret_cast<const float2*>(b + (lane << 1));
    float2 r  = make_float2(w.x * sl + dn * sum.x + bb.x,
                            w.y * sl + dn * sum.y + bb.y);
    *reinterpret_cast<float2*>(g_out + ((size_t)node << 6) + (lane << 1)) = r;
}

// ---------------------------------------------------------------------------
// 5) final gather
// ---------------------------------------------------------------------------
__global__ void gather_kernel(const int* __restrict__ x,
                              float* __restrict__ out, int nidx) {
    int idx = blockIdx.x * blockDim.x + threadIdx.x;
    int i = idx >> 4;
    int q = idx & 15;
    if (i >= nidx) return;
    int nd = x[i];
    float4 v = *reinterpret_cast<const float4*>(g_out + ((size_t)nd << 6) + (q << 2));
    *reinterpret_cast<float4*>(out + ((size_t)i << 6) + (q << 2)) = v;
}

// ---------------------------------------------------------------------------
extern "C" void kernel_launch(void* const* d_in, const int* in_sizes, int n_in,
                              void* d_out, int out_size) {
    const float* features   = (const float*)d_in[0];
    const int*   edge_index = (const int*)  d_in[1];
    const float* W          = (const float*)d_in[2];
    const float* b          = (const float*)d_in[3];
    const int*   x          = (const int*)  d_in[4];
    float*       out        = (float*)d_out;

    const int N  = in_sizes[0] / FIN;
    const int E  = in_sizes[1] / 2;
    const int NX = in_sizes[4];

    const int* src = edge_index;
    const int* dst = edge_index + E;
    const int NB = (N + 1023) / 1024;

    int nDeg = (E + 1023) / 1024;
    degwsplit_kernel<<<nDeg + 64, 256>>>(dst, E, W, nDeg);

    scan1_kernel<<<NB, 256>>>(N);
    scan2_kernel<<<1, 128>>>(NB);
    scan3_kernel<<<(N + 255) / 256, 256>>>(N);

    int nGemm = (N + 127) / 128;
    int nFillNeeded = (E + 1023) / 1024;
    if (nGemm * 4 < nFillNeeded) nGemm = (nFillNeeded + 3) / 4;
    gemm_fill_kernel<<<nGemm * 5, 256>>>(features, N, src, dst, E);

    long long agg_threads = (long long)N * 32;
    aggregate_kernel<<<(int)((agg_threads + 255) / 256), 256>>>(b, N);

    gather_kernel<<<(NX * 16 + 255) / 256, 256>>>(x, out, NX);
}